// round 4
// baseline (speedup 1.0000x reference)
#include <cuda_runtime.h>

#define D   256
#define BB  4
#define LX  512
#define LM  512

// Scratch: projected queries/keys (allocation-free requirement -> device globals)
__device__ float g_Q[BB * LX * D];   // (b*LX + x, d) = x @ W1^T + b1
__device__ float g_K[BB * LM * D];   // (b*LM + m, d) = memory @ W2^T

__device__ __forceinline__ float fast_tanh(float v) {
    float y;
    asm("tanh.approx.f32 %0, %1;" : "=f"(y) : "f"(v));
    return y;
}

// ----------------------------------------------------------------------------
// Kernel A: C[r][e] = sum_d A[r][d] * W[e][d] (+ bias[e])
// Both operands are d-contiguous (A @ W^T). Tile 64x64, BK=16, 4x4 per thread.
// grid.z = 0 -> (x, W1, b1) -> g_Q ; grid.z = 1 -> (memory, W2, none) -> g_K
// ----------------------------------------------------------------------------
__global__ __launch_bounds__(256) void gemm_qk(
    const float* __restrict__ x,   const float* __restrict__ W1,
    const float* __restrict__ b1,  const float* __restrict__ mem,
    const float* __restrict__ W2)
{
    const float* A; const float* W; const float* bias; float* C;
    if (blockIdx.z == 0) { A = x;   W = W1; bias = b1;      C = g_Q; }
    else                 { A = mem; W = W2; bias = nullptr; C = g_K; }

    __shared__ float As[16][64];   // [k][m]
    __shared__ float Bs[16][64];   // [k][n]

    int tid = threadIdx.x;
    int m0 = blockIdx.x * 64;
    int n0 = blockIdx.y * 64;
    int tx = tid & 15;       // n-group (cols)
    int ty = tid >> 4;       // m-group (rows)

    float acc[4][4] = {};

    int lr = tid >> 2;           // 0..63 load row
    int lc = (tid & 3) << 2;     // 0,4,8,12 load col4
    const float* Ap = A + (m0 + lr) * D + lc;
    const float* Wp = W + (n0 + lr) * D + lc;

    for (int k0 = 0; k0 < D; k0 += 16) {
        float4 av = *(const float4*)(Ap + k0);
        float4 wv = *(const float4*)(Wp + k0);
        As[lc + 0][lr] = av.x; As[lc + 1][lr] = av.y;
        As[lc + 2][lr] = av.z; As[lc + 3][lr] = av.w;
        Bs[lc + 0][lr] = wv.x; Bs[lc + 1][lr] = wv.y;
        Bs[lc + 2][lr] = wv.z; Bs[lc + 3][lr] = wv.w;
        __syncthreads();
        #pragma unroll
        for (int k = 0; k < 16; k++) {
            float4 a4 = *(const float4*)&As[k][ty << 2];
            float4 b4 = *(const float4*)&Bs[k][tx << 2];
            float av4[4] = {a4.x, a4.y, a4.z, a4.w};
            float bv4[4] = {b4.x, b4.y, b4.z, b4.w};
            #pragma unroll
            for (int i = 0; i < 4; i++)
                #pragma unroll
                for (int j = 0; j < 4; j++)
                    acc[i][j] = fmaf(av4[i], bv4[j], acc[i][j]);
        }
        __syncthreads();
    }

    int n = n0 + (tx << 2);
    float bx = 0.f, by = 0.f, bz = 0.f, bw = 0.f;
    if (bias) { bx = bias[n]; by = bias[n + 1]; bz = bias[n + 2]; bw = bias[n + 3]; }
    #pragma unroll
    for (int i = 0; i < 4; i++) {
        int r = m0 + (ty << 2) + i;
        float4 o;
        o.x = acc[i][0] + bx; o.y = acc[i][1] + by;
        o.z = acc[i][2] + bz; o.w = acc[i][3] + bw;
        *(float4*)&C[r * D + n] = o;
    }
}

// ----------------------------------------------------------------------------
// Kernel B: S[b, x, m] = sum_d Wt[d] * tanh(Q[b,x,d] + K[b,m,d]); mask epilogue.
// 64x64 output tile per block, 256 threads, 4x4 per thread, d-chunks of 32.
// ----------------------------------------------------------------------------
__global__ __launch_bounds__(256) void attn_kernel(
    const float* __restrict__ Wt, const int* __restrict__ mask,
    float* __restrict__ out)
{
    __shared__ float Qs[32][64];   // [k][x-row]
    __shared__ float Ks[32][64];   // [k][m-col]
    __shared__ float wts[32];

    int b  = blockIdx.z;
    int x0 = blockIdx.y * 64;
    int m0 = blockIdx.x * 64;
    int tid = threadIdx.x;
    int tx = tid & 15;     // m-cols group
    int ty = tid >> 4;     // x-rows group

    const float* Qbase = g_Q + (b * LX + x0) * D;
    const float* Kbase = g_K + (b * LM + m0) * D;

    float acc[4][4] = {};

    int lr = tid >> 3;           // 0..31
    int lc = (tid & 7) << 2;     // 0..28

    for (int k0 = 0; k0 < D; k0 += 32) {
        if (tid < 32) wts[tid] = Wt[k0 + tid];
        #pragma unroll
        for (int p = 0; p < 2; p++) {
            int row = lr + p * 32;
            float4 qv = *(const float4*)(Qbase + row * D + k0 + lc);
            Qs[lc + 0][row] = qv.x; Qs[lc + 1][row] = qv.y;
            Qs[lc + 2][row] = qv.z; Qs[lc + 3][row] = qv.w;
            float4 kv = *(const float4*)(Kbase + row * D + k0 + lc);
            Ks[lc + 0][row] = kv.x; Ks[lc + 1][row] = kv.y;
            Ks[lc + 2][row] = kv.z; Ks[lc + 3][row] = kv.w;
        }
        __syncthreads();
        #pragma unroll
        for (int k = 0; k < 32; k++) {
            float4 qa = *(const float4*)&Qs[k][ty << 2];
            float4 kb = *(const float4*)&Ks[k][tx << 2];
            float w = wts[k];
            float qf[4] = {qa.x, qa.y, qa.z, qa.w};
            float kf[4] = {kb.x, kb.y, kb.z, kb.w};
            #pragma unroll
            for (int i = 0; i < 4; i++)
                #pragma unroll
                for (int j = 0; j < 4; j++)
                    acc[i][j] = fmaf(w, fast_tanh(qf[i] + kf[j]), acc[i][j]);
        }
        __syncthreads();
    }

    int mcol = m0 + (tx << 2);
    int4 mk = *(const int4*)&mask[b * LM + mcol];
    #pragma unroll
    for (int i = 0; i < 4; i++) {
        int xr = x0 + (ty << 2) + i;
        float4 o;
        o.x = (mk.x != 0) ? acc[i][0] : -10000.0f;
        o.y = (mk.y != 0) ? acc[i][1] : -10000.0f;
        o.z = (mk.z != 0) ? acc[i][2] : -10000.0f;
        o.w = (mk.w != 0) ? acc[i][3] : -10000.0f;
        *(float4*)&out[(b * LX + xr) * LM + mcol] = o;
    }
}

extern "C" void kernel_launch(void* const* d_in, const int* in_sizes, int n_in,
                              void* d_out, int out_size)
{
    const float* x      = (const float*)d_in[0];
    const float* memory = (const float*)d_in[1];
    const int*   mask   = (const int*)d_in[2];
    const float* W1     = (const float*)d_in[3];
    const float* b1     = (const float*)d_in[4];
    const float* W2     = (const float*)d_in[5];
    const float* Wt     = (const float*)d_in[6];
    float* out = (float*)d_out;

    dim3 g1(BB * LX / 64, D / 64, 2);      // 32 x 4 x 2 = 256 blocks
    gemm_qk<<<g1, 256>>>(x, W1, b1, memory, W2);

    dim3 g2(LM / 64, LX / 64, BB);          // 8 x 8 x 4 = 256 blocks
    attn_kernel<<<g2, 256>>>(Wt, mask, out);
}

// round 5
// speedup vs baseline: 1.4556x; 1.4556x over previous
#include <cuda_runtime.h>

#define D   256
#define BB  4
#define LX  512
#define LM  512

// Scratch (allocation-free requirement -> device globals)
__device__ float g_Q[BB * LX * D];   // (b*LX + x, d)
__device__ float g_K[BB * LM * D];   // (b*LM + r, d), r = COMPACTED valid-m index
__device__ int   g_cidx[BB * LM];    // compacted -> original m index (padded w/ 0)
__device__ int   g_cnt[BB];          // valid count per batch

__device__ __forceinline__ float fast_tanh(float v) {
    float y;
    asm("tanh.approx.f32 %0, %1;" : "=f"(y) : "f"(v));
    return y;
}

// ----------------------------------------------------------------------------
// Fill output with -10000 (masked default). 1M floats via float4.
// ----------------------------------------------------------------------------
__global__ __launch_bounds__(256) void fill_kernel(float4* __restrict__ out) {
    int i = blockIdx.x * 256 + threadIdx.x;
    out[i] = make_float4(-10000.0f, -10000.0f, -10000.0f, -10000.0f);
}

// ----------------------------------------------------------------------------
// Compact mask: per batch, ballot-scan 512 entries -> cidx list + count.
// One block of 512 threads per batch.
// ----------------------------------------------------------------------------
__global__ __launch_bounds__(512) void compact_kernel(const int* __restrict__ mask) {
    int b = blockIdx.x;
    int t = threadIdx.x;
    int lane = t & 31, wid = t >> 5;

    int valid = (mask[b * LM + t] != 0);
    unsigned bal = __ballot_sync(0xffffffffu, valid);

    __shared__ int wcnt[16];
    __shared__ int woff[16];
    __shared__ int s_cnt;
    if (lane == 0) wcnt[wid] = __popc(bal);
    __syncthreads();
    if (t == 0) {
        int s = 0;
        #pragma unroll
        for (int i = 0; i < 16; i++) { woff[i] = s; s += wcnt[i]; }
        s_cnt = s;
        g_cnt[b] = s;
    }
    __syncthreads();
    int pos = woff[wid] + __popc(bal & ((1u << lane) - 1u));
    if (valid) g_cidx[b * LM + pos] = t;
    // pad up to next multiple of 64 with index 0 (safe, never stored)
    int cnt = s_cnt;
    int cpad = (cnt + 63) & ~63;
    if (t >= cnt && t < cpad) g_cidx[b * LM + t] = 0;
}

// ----------------------------------------------------------------------------
// Kernel A: projections. z==0: g_Q = x @ W1^T + b1 (all rows).
//           z==1: g_K[compacted] = memory[cidx] @ W2^T (valid rows only).
// Tile 64x64, BK=16, 4x4 per thread.
// ----------------------------------------------------------------------------
__global__ __launch_bounds__(256) void gemm_qk(
    const float* __restrict__ x,   const float* __restrict__ W1,
    const float* __restrict__ b1,  const float* __restrict__ mem,
    const float* __restrict__ W2)
{
    __shared__ float As[16][64];   // [k][m]
    __shared__ float Bs[16][64];   // [k][n]

    int tid = threadIdx.x;
    int n0 = blockIdx.y * 64;
    int tx = tid & 15;       // n-group
    int ty = tid >> 4;       // m-group
    int lr = tid >> 2;       // 0..63 load row
    int lc = (tid & 3) << 2; // 0,4,8,12

    const float* W; const float* bias; float* C;
    const float* Ap;          // this thread's load-row base
    int crow;                 // this block's output row base (into C)

    if (blockIdx.z == 0) {
        int m0 = blockIdx.x * 64;
        W = W1; bias = b1; C = g_Q;
        Ap = x + (m0 + lr) * D + lc;
        crow = m0;
    } else {
        int b  = blockIdx.x >> 3;
        int rt = blockIdx.x & 7;
        if (rt * 64 >= g_cnt[b]) return;            // tile fully masked out
        W = W2; bias = nullptr; C = g_K;
        int orig = g_cidx[b * LM + rt * 64 + lr];   // gather original memory row
        Ap = mem + (b * LM + orig) * D + lc;
        crow = b * LM + rt * 64;
    }

    float acc[4][4] = {};
    const float* Wp = W + (n0 + lr) * D + lc;

    for (int k0 = 0; k0 < D; k0 += 16) {
        float4 av = *(const float4*)(Ap + k0);
        float4 wv = *(const float4*)(Wp + k0);
        As[lc + 0][lr] = av.x; As[lc + 1][lr] = av.y;
        As[lc + 2][lr] = av.z; As[lc + 3][lr] = av.w;
        Bs[lc + 0][lr] = wv.x; Bs[lc + 1][lr] = wv.y;
        Bs[lc + 2][lr] = wv.z; Bs[lc + 3][lr] = wv.w;
        __syncthreads();
        #pragma unroll
        for (int k = 0; k < 16; k++) {
            float4 a4 = *(const float4*)&As[k][ty << 2];
            float4 b4 = *(const float4*)&Bs[k][tx << 2];
            float av4[4] = {a4.x, a4.y, a4.z, a4.w};
            float bv4[4] = {b4.x, b4.y, b4.z, b4.w};
            #pragma unroll
            for (int i = 0; i < 4; i++)
                #pragma unroll
                for (int j = 0; j < 4; j++)
                    acc[i][j] = fmaf(av4[i], bv4[j], acc[i][j]);
        }
        __syncthreads();
    }

    int n = n0 + (tx << 2);
    float bx = 0.f, by = 0.f, bz = 0.f, bw = 0.f;
    if (bias) { bx = bias[n]; by = bias[n + 1]; bz = bias[n + 2]; bw = bias[n + 3]; }
    #pragma unroll
    for (int i = 0; i < 4; i++) {
        int r = crow + (ty << 2) + i;
        float4 o;
        o.x = acc[i][0] + bx; o.y = acc[i][1] + by;
        o.z = acc[i][2] + bz; o.w = acc[i][3] + bw;
        *(float4*)&C[r * D + n] = o;
    }
}

// ----------------------------------------------------------------------------
// Kernel B: S over COMPACTED columns only.
// S[b, x, cidx[j]] = sum_d Wt[d] * tanh(Q[b,x,d] + K[b,j,d]) for j < cnt[b].
// 64x64 tile, 256 threads, 4x4 per thread, d-chunks of 32. Early-exit tiles.
// ----------------------------------------------------------------------------
__global__ __launch_bounds__(256) void attn_kernel(
    const float* __restrict__ Wt, float* __restrict__ out)
{
    int b   = blockIdx.z;
    int cnt = g_cnt[b];
    int m0  = blockIdx.x * 64;          // compacted-column tile base
    if (m0 >= cnt) return;

    __shared__ float Qs[32][64];
    __shared__ float Ks[32][64];
    __shared__ float wts[32];

    int x0 = blockIdx.y * 64;
    int tid = threadIdx.x;
    int tx = tid & 15;     // compacted-col group
    int ty = tid >> 4;     // x-row group

    const float* Qbase = g_Q + (b * LX + x0) * D;
    const float* Kbase = g_K + (b * LM + m0) * D;   // compacted: contiguous rows

    float acc[4][4] = {};

    int lr = tid >> 3;           // 0..31
    int lc = (tid & 7) << 2;     // 0..28

    for (int k0 = 0; k0 < D; k0 += 32) {
        if (tid < 32) wts[tid] = Wt[k0 + tid];
        #pragma unroll
        for (int p = 0; p < 2; p++) {
            int row = lr + p * 32;
            float4 qv = *(const float4*)(Qbase + row * D + k0 + lc);
            Qs[lc + 0][row] = qv.x; Qs[lc + 1][row] = qv.y;
            Qs[lc + 2][row] = qv.z; Qs[lc + 3][row] = qv.w;
            float4 kv = *(const float4*)(Kbase + row * D + k0 + lc);
            Ks[lc + 0][row] = kv.x; Ks[lc + 1][row] = kv.y;
            Ks[lc + 2][row] = kv.z; Ks[lc + 3][row] = kv.w;
        }
        __syncthreads();
        #pragma unroll
        for (int k = 0; k < 32; k++) {
            float4 qa = *(const float4*)&Qs[k][ty << 2];
            float4 kb = *(const float4*)&Ks[k][tx << 2];
            float w = wts[k];
            float qf[4] = {qa.x, qa.y, qa.z, qa.w};
            float kf[4] = {kb.x, kb.y, kb.z, kb.w};
            #pragma unroll
            for (int i = 0; i < 4; i++)
                #pragma unroll
                for (int j = 0; j < 4; j++)
                    acc[i][j] = fmaf(w, fast_tanh(qf[i] + kf[j]), acc[i][j]);
        }
        __syncthreads();
    }

    // Scatter epilogue: compacted col j -> original column cidx[b][j]
    #pragma unroll
    for (int jj = 0; jj < 4; jj++) {
        int j = m0 + (tx << 2) + jj;
        if (j < cnt) {
            int m = g_cidx[b * LM + j];
            #pragma unroll
            for (int i = 0; i < 4; i++) {
                int xr = x0 + (ty << 2) + i;
                out[(b * LX + xr) * LM + m] = acc[i][jj];
            }
        }
    }
}

extern "C" void kernel_launch(void* const* d_in, const int* in_sizes, int n_in,
                              void* d_out, int out_size)
{
    const float* x      = (const float*)d_in[0];
    const float* memory = (const float*)d_in[1];
    const int*   mask   = (const int*)d_in[2];
    const float* W1     = (const float*)d_in[3];
    const float* b1     = (const float*)d_in[4];
    const float* W2     = (const float*)d_in[5];
    const float* Wt     = (const float*)d_in[6];
    float* out = (float*)d_out;

    // 1) blanket -10000
    fill_kernel<<<(BB * LX * LM / 4) / 256, 256>>>((float4*)out);

    // 2) mask compaction
    compact_kernel<<<BB, 512>>>(mask);

    // 3) projections: z=0 Q (32 row tiles), z=1 K (4 batches x 8 row tiles, early-exit)
    dim3 g1(32, D / 64, 2);
    gemm_qk<<<g1, 256>>>(x, W1, b1, memory, W2);

    // 4) attention on compacted columns
    dim3 g2(LM / 64, LX / 64, BB);
    attn_kernel<<<g2, 256>>>(Wt, out);
}

// round 6
// speedup vs baseline: 1.5678x; 1.0770x over previous
#include <cuda_runtime.h>

#define D   256
#define BB  4
#define LX  512
#define LM  512

// Scratch (allocation-free requirement -> device globals)
__device__ float g_Q[BB * LX * D];   // (b*LX + x, d)
__device__ float g_K[BB * LM * D];   // (b*LM + r, d), r = COMPACTED valid-m index
__device__ int   g_cidx[BB * LM];    // compacted -> original m index (padded w/ 0)
__device__ int   g_cnt[BB];          // valid count per batch

__device__ __forceinline__ float fast_tanh(float v) {
    float y;
    asm("tanh.approx.f32 %0, %1;" : "=f"(y) : "f"(v));
    return y;
}

// ----------------------------------------------------------------------------
// Fill output with -10000 (masked default).
// ----------------------------------------------------------------------------
__global__ __launch_bounds__(256) void fill_kernel(float4* __restrict__ out) {
    int i = blockIdx.x * 256 + threadIdx.x;
    out[i] = make_float4(-10000.0f, -10000.0f, -10000.0f, -10000.0f);
}

// ----------------------------------------------------------------------------
// Compact mask: per batch, ballot-scan 512 entries -> cidx list + count.
// ----------------------------------------------------------------------------
__global__ __launch_bounds__(512) void compact_kernel(const int* __restrict__ mask) {
    int b = blockIdx.x;
    int t = threadIdx.x;
    int lane = t & 31, wid = t >> 5;

    int valid = (mask[b * LM + t] != 0);
    unsigned bal = __ballot_sync(0xffffffffu, valid);

    __shared__ int wcnt[16];
    __shared__ int woff[16];
    __shared__ int s_cnt;
    if (lane == 0) wcnt[wid] = __popc(bal);
    __syncthreads();
    if (t == 0) {
        int s = 0;
        #pragma unroll
        for (int i = 0; i < 16; i++) { woff[i] = s; s += wcnt[i]; }
        s_cnt = s;
        g_cnt[b] = s;
    }
    __syncthreads();
    int pos = woff[wid] + __popc(bal & ((1u << lane) - 1u));
    if (valid) g_cidx[b * LM + pos] = t;
    int cnt = s_cnt;
    int cpad = (cnt + 63) & ~63;
    if (t >= cnt && t < cpad) g_cidx[b * LM + t] = 0;
}

// ----------------------------------------------------------------------------
// Kernel A: projections. z==0: g_Q = x @ W1^T + b1 (all rows).
//           z==1: g_K[compacted] = memory[cidx] @ W2^T (valid rows only).
// Tile 64x64, BK=16, 4x4 per thread.
// ----------------------------------------------------------------------------
__global__ __launch_bounds__(256) void gemm_qk(
    const float* __restrict__ x,   const float* __restrict__ W1,
    const float* __restrict__ b1,  const float* __restrict__ mem,
    const float* __restrict__ W2)
{
    __shared__ float As[16][64];
    __shared__ float Bs[16][64];

    int tid = threadIdx.x;
    int n0 = blockIdx.y * 64;
    int tx = tid & 15;
    int ty = tid >> 4;
    int lr = tid >> 2;
    int lc = (tid & 3) << 2;

    const float* W; const float* bias; float* C;
    const float* Ap;
    int crow;

    if (blockIdx.z == 0) {
        int m0 = blockIdx.x * 64;
        W = W1; bias = b1; C = g_Q;
        Ap = x + (m0 + lr) * D + lc;
        crow = m0;
    } else {
        int b  = blockIdx.x >> 3;
        int rt = blockIdx.x & 7;
        if (rt * 64 >= g_cnt[b]) return;
        W = W2; bias = nullptr; C = g_K;
        int orig = g_cidx[b * LM + rt * 64 + lr];
        Ap = mem + (b * LM + orig) * D + lc;
        crow = b * LM + rt * 64;
    }

    float acc[4][4] = {};
    const float* Wp = W + (n0 + lr) * D + lc;

    for (int k0 = 0; k0 < D; k0 += 16) {
        float4 av = *(const float4*)(Ap + k0);
        float4 wv = *(const float4*)(Wp + k0);
        As[lc + 0][lr] = av.x; As[lc + 1][lr] = av.y;
        As[lc + 2][lr] = av.z; As[lc + 3][lr] = av.w;
        Bs[lc + 0][lr] = wv.x; Bs[lc + 1][lr] = wv.y;
        Bs[lc + 2][lr] = wv.z; Bs[lc + 3][lr] = wv.w;
        __syncthreads();
        #pragma unroll
        for (int k = 0; k < 16; k++) {
            float4 a4 = *(const float4*)&As[k][ty << 2];
            float4 b4 = *(const float4*)&Bs[k][tx << 2];
            float av4[4] = {a4.x, a4.y, a4.z, a4.w};
            float bv4[4] = {b4.x, b4.y, b4.z, b4.w};
            #pragma unroll
            for (int i = 0; i < 4; i++)
                #pragma unroll
                for (int j = 0; j < 4; j++)
                    acc[i][j] = fmaf(av4[i], bv4[j], acc[i][j]);
        }
        __syncthreads();
    }

    int n = n0 + (tx << 2);
    float bx = 0.f, by = 0.f, bz = 0.f, bw = 0.f;
    if (bias) { bx = bias[n]; by = bias[n + 1]; bz = bias[n + 2]; bw = bias[n + 3]; }
    #pragma unroll
    for (int i = 0; i < 4; i++) {
        int r = crow + (ty << 2) + i;
        float4 o;
        o.x = acc[i][0] + bx; o.y = acc[i][1] + by;
        o.z = acc[i][2] + bz; o.w = acc[i][3] + bw;
        *(float4*)&C[r * D + n] = o;
    }
}

// ----------------------------------------------------------------------------
// Kernel B: S over COMPACTED columns only. 64x64 tile, 512 threads (16 warps),
// 2x4 micro-tile per thread -> 4 warps/SMSP on working SMs to hide MUFU latency.
// ----------------------------------------------------------------------------
__global__ __launch_bounds__(512) void attn_kernel(
    const float* __restrict__ Wt, float* __restrict__ out)
{
    int b   = blockIdx.z;
    int cnt = g_cnt[b];
    int m0  = blockIdx.x * 64;
    if (m0 >= cnt) return;

    __shared__ float Qs[32][64];
    __shared__ float Ks[32][64];
    __shared__ float wts[32];

    int x0 = blockIdx.y * 64;
    int tid = threadIdx.x;
    int tx = tid & 15;     // 16 groups * 4 cols
    int ty = tid >> 4;     // 32 groups * 2 rows

    const float* Qbase = g_Q + (b * LX + x0) * D;
    const float* Kbase = g_K + (b * LM + m0) * D;

    float acc[2][4] = {};

    int lr = tid >> 3;           // 0..63 load row
    int lc = (tid & 7) << 2;     // 0..28

    for (int k0 = 0; k0 < D; k0 += 32) {
        if (tid < 32) wts[tid] = Wt[k0 + tid];
        float4 qv = *(const float4*)(Qbase + lr * D + k0 + lc);
        Qs[lc + 0][lr] = qv.x; Qs[lc + 1][lr] = qv.y;
        Qs[lc + 2][lr] = qv.z; Qs[lc + 3][lr] = qv.w;
        float4 kv = *(const float4*)(Kbase + lr * D + k0 + lc);
        Ks[lc + 0][lr] = kv.x; Ks[lc + 1][lr] = kv.y;
        Ks[lc + 2][lr] = kv.z; Ks[lc + 3][lr] = kv.w;
        __syncthreads();
        #pragma unroll
        for (int k = 0; k < 32; k++) {
            float2 qa = *(const float2*)&Qs[k][ty << 1];   // 2 rows (warp-broadcast)
            float4 kb = *(const float4*)&Ks[k][tx << 2];   // 4 cols
            float w = wts[k];
            float qf[2] = {qa.x, qa.y};
            float kf[4] = {kb.x, kb.y, kb.z, kb.w};
            #pragma unroll
            for (int i = 0; i < 2; i++)
                #pragma unroll
                for (int j = 0; j < 4; j++)
                    acc[i][j] = fmaf(w, fast_tanh(qf[i] + kf[j]), acc[i][j]);
        }
        __syncthreads();
    }

    // Scatter epilogue: compacted col j -> original column cidx[b][j]
    #pragma unroll
    for (int jj = 0; jj < 4; jj++) {
        int j = m0 + (tx << 2) + jj;
        if (j < cnt) {
            int m = g_cidx[b * LM + j];
            #pragma unroll
            for (int i = 0; i < 2; i++) {
                int xr = x0 + (ty << 1) + i;
                out[(b * LX + xr) * LM + m] = acc[i][jj];
            }
        }
    }
}

extern "C" void kernel_launch(void* const* d_in, const int* in_sizes, int n_in,
                              void* d_out, int out_size)
{
    const float* x      = (const float*)d_in[0];
    const float* memory = (const float*)d_in[1];
    const int*   mask   = (const int*)d_in[2];
    const float* W1     = (const float*)d_in[3];
    const float* b1     = (const float*)d_in[4];
    const float* W2     = (const float*)d_in[5];
    const float* W2_    = (const float*)d_in[5];
    const float* Wt     = (const float*)d_in[6];
    (void)W2_;
    float* out = (float*)d_out;

    fill_kernel<<<(BB * LX * LM / 4) / 256, 256>>>((float4*)out);
    compact_kernel<<<BB, 512>>>(mask);

    dim3 g1(32, D / 64, 2);
    gemm_qk<<<g1, 256>>>(x, W1, b1, memory, W2);

    dim3 g2(LM / 64, LX / 64, BB);
    attn_kernel<<<g2, 512>>>(Wt, out);
}

// round 9
// speedup vs baseline: 1.8014x; 1.1490x over previous
#include <cuda_runtime.h>

#define D   256
#define BB  4
#define LX  512
#define LM  512

// Scratch (allocation-free requirement -> device globals)
__device__ float g_Q[BB * LX * D];   // (b*LX + x, d)
__device__ float g_K[BB * LM * D];   // (b*LM + r, d), r = COMPACTED valid-m index
__device__ int   g_cidx[BB * LM];    // compacted -> original m index (padded w/ 0)
__device__ int   g_cnt[BB];          // valid count per batch

__device__ __forceinline__ float fast_tanh(float v) {
    float y;
    asm("tanh.approx.f32 %0, %1;" : "=f"(y) : "f"(v));
    return y;
}

// ----------------------------------------------------------------------------
// Fill output with -10000 (masked default).
// ----------------------------------------------------------------------------
__global__ __launch_bounds__(256) void fill_kernel(float4* __restrict__ out) {
    int i = blockIdx.x * 256 + threadIdx.x;
    out[i] = make_float4(-10000.0f, -10000.0f, -10000.0f, -10000.0f);
}

// ----------------------------------------------------------------------------
// Compact mask: per batch, ballot-scan 512 entries -> cidx list + count.
// ----------------------------------------------------------------------------
__global__ __launch_bounds__(512) void compact_kernel(const int* __restrict__ mask) {
    int b = blockIdx.x;
    int t = threadIdx.x;
    int lane = t & 31, wid = t >> 5;

    int valid = (mask[b * LM + t] != 0);
    unsigned bal = __ballot_sync(0xffffffffu, valid);

    __shared__ int wcnt[16];
    __shared__ int woff[16];
    __shared__ int s_cnt;
    if (lane == 0) wcnt[wid] = __popc(bal);
    __syncthreads();
    if (t == 0) {
        int s = 0;
        #pragma unroll
        for (int i = 0; i < 16; i++) { woff[i] = s; s += wcnt[i]; }
        s_cnt = s;
        g_cnt[b] = s;
    }
    __syncthreads();
    int pos = woff[wid] + __popc(bal & ((1u << lane) - 1u));
    if (valid) g_cidx[b * LM + pos] = t;
    int cnt = s_cnt;
    int cpad = (cnt + 63) & ~63;
    if (t >= cnt && t < cpad) g_cidx[b * LM + t] = 0;
}

// ----------------------------------------------------------------------------
// Kernel A: projections. z==0: g_Q = x @ W1^T + b1 (all rows).
//           z==1: g_K[compacted] = memory[cidx] @ W2^T (valid rows only).
// Tile 64x64, BK=16, 4x4 per thread.
// ----------------------------------------------------------------------------
__global__ __launch_bounds__(256) void gemm_qk(
    const float* __restrict__ x,   const float* __restrict__ W1,
    const float* __restrict__ b1,  const float* __restrict__ mem,
    const float* __restrict__ W2)
{
    __shared__ float As[16][64];
    __shared__ float Bs[16][64];

    int tid = threadIdx.x;
    int n0 = blockIdx.y * 64;
    int tx = tid & 15;
    int ty = tid >> 4;
    int lr = tid >> 2;
    int lc = (tid & 3) << 2;

    const float* W; const float* bias; float* C;
    const float* Ap;
    int crow;

    if (blockIdx.z == 0) {
        int m0 = blockIdx.x * 64;
        W = W1; bias = b1; C = g_Q;
        Ap = x + (m0 + lr) * D + lc;
        crow = m0;
    } else {
        int b  = blockIdx.x >> 3;
        int rt = blockIdx.x & 7;
        if (rt * 64 >= g_cnt[b]) return;
        W = W2; bias = nullptr; C = g_K;
        int orig = g_cidx[b * LM + rt * 64 + lr];
        Ap = mem + (b * LM + orig) * D + lc;
        crow = b * LM + rt * 64;
    }

    float acc[4][4] = {};
    const float* Wp = W + (n0 + lr) * D + lc;

    for (int k0 = 0; k0 < D; k0 += 16) {
        float4 av = *(const float4*)(Ap + k0);
        float4 wv = *(const float4*)(Wp + k0);
        As[lc + 0][lr] = av.x; As[lc + 1][lr] = av.y;
        As[lc + 2][lr] = av.z; As[lc + 3][lr] = av.w;
        Bs[lc + 0][lr] = wv.x; Bs[lc + 1][lr] = wv.y;
        Bs[lc + 2][lr] = wv.z; Bs[lc + 3][lr] = wv.w;
        __syncthreads();
        #pragma unroll
        for (int k = 0; k < 16; k++) {
            float4 a4 = *(const float4*)&As[k][ty << 2];
            float4 b4 = *(const float4*)&Bs[k][tx << 2];
            float av4[4] = {a4.x, a4.y, a4.z, a4.w};
            float bv4[4] = {b4.x, b4.y, b4.z, b4.w};
            #pragma unroll
            for (int i = 0; i < 4; i++)
                #pragma unroll
                for (int j = 0; j < 4; j++)
                    acc[i][j] = fmaf(av4[i], bv4[j], acc[i][j]);
        }
        __syncthreads();
    }

    int n = n0 + (tx << 2);
    float bx = 0.f, by = 0.f, bz = 0.f, bw = 0.f;
    if (bias) { bx = bias[n]; by = bias[n + 1]; bz = bias[n + 2]; bw = bias[n + 3]; }
    #pragma unroll
    for (int i = 0; i < 4; i++) {
        int r = crow + (ty << 2) + i;
        float4 o;
        o.x = acc[i][0] + bx; o.y = acc[i][1] + by;
        o.z = acc[i][2] + bz; o.w = acc[i][3] + bw;
        *(float4*)&C[r * D + n] = o;
    }
}

// ----------------------------------------------------------------------------
// Kernel B: front-packed 1-D grid of 32x64 work items (32 x-rows, 64 compacted
// cols). All work ids < total are live; dead blocks exit instantly -> every SM
// carries <= ceil(total/148) MUFU-bound items. 256 threads, 2x4 micro-tile.
// ----------------------------------------------------------------------------
__global__ __launch_bounds__(256) void attn_kernel(
    const float* __restrict__ Wt, float* __restrict__ out)
{
    // per-block work decode from g_cnt (registers only)
    int4 cv = *(const int4*)g_cnt;
    int n0t = (cv.x + 63) >> 6;
    int n1t = (cv.y + 63) >> 6;
    int n2t = (cv.z + 63) >> 6;
    int n3t = (cv.w + 63) >> 6;
    int total_tiles = n0t + n1t + n2t + n3t;

    int work = blockIdx.x;
    if (work >= (total_tiles << 4)) return;      // 16 x-tiles per column tile

    int tile = work >> 4;
    int xt   = work & 15;

    int b, mt, cnt;
    if (tile < n0t)                   { b = 0; mt = tile;                   cnt = cv.x; }
    else if (tile < n0t + n1t)        { b = 1; mt = tile - n0t;             cnt = cv.y; }
    else if (tile < n0t + n1t + n2t)  { b = 2; mt = tile - n0t - n1t;       cnt = cv.z; }
    else                              { b = 3; mt = tile - n0t - n1t - n2t; cnt = cv.w; }

    int m0 = mt << 6;      // compacted column base (64 wide)
    int x0 = xt << 5;      // x-row base (32 tall)

    __shared__ float Qs[32][32];   // [k][x-row]
    __shared__ float Ks[32][64];   // [k][m-col]
    __shared__ float wts[32];

    int tid = threadIdx.x;
    int tx = tid & 15;     // 16 groups * 4 cols
    int ty = tid >> 4;     // 16 groups * 2 rows

    const float* Qbase = g_Q + (b * LX + x0) * D;
    const float* Kbase = g_K + (b * LM + m0) * D;

    float acc[2][4] = {};

    int qlr = tid >> 3;          // 0..31 (Q row)
    int klr = tid >> 3;          // 0..31 (K rows: klr and klr+32)
    int lc  = (tid & 7) << 2;    // 0..28

    for (int k0 = 0; k0 < D; k0 += 32) {
        if (tid < 32) wts[tid] = Wt[k0 + tid];
        float4 qv = *(const float4*)(Qbase + qlr * D + k0 + lc);
        Qs[lc + 0][qlr] = qv.x; Qs[lc + 1][qlr] = qv.y;
        Qs[lc + 2][qlr] = qv.z; Qs[lc + 3][qlr] = qv.w;
        #pragma unroll
        for (int p = 0; p < 2; p++) {
            int row = klr + p * 32;
            float4 kv = *(const float4*)(Kbase + row * D + k0 + lc);
            Ks[lc + 0][row] = kv.x; Ks[lc + 1][row] = kv.y;
            Ks[lc + 2][row] = kv.z; Ks[lc + 3][row] = kv.w;
        }
        __syncthreads();
        #pragma unroll
        for (int k = 0; k < 32; k++) {
            float2 qa = *(const float2*)&Qs[k][ty << 1];   // 2 rows
            float4 kb = *(const float4*)&Ks[k][tx << 2];   // 4 cols
            float w = wts[k];
            float qf[2] = {qa.x, qa.y};
            float kf[4] = {kb.x, kb.y, kb.z, kb.w};
            #pragma unroll
            for (int i = 0; i < 2; i++)
                #pragma unroll
                for (int j = 0; j < 4; j++)
                    acc[i][j] = fmaf(w, fast_tanh(qf[i] + kf[j]), acc[i][j]);
        }
        __syncthreads();
    }

    // Scatter epilogue: compacted col j -> original column cidx[b][j]
    #pragma unroll
    for (int jj = 0; jj < 4; jj++) {
        int j = m0 + (tx << 2) + jj;
        if (j < cnt) {
            int m = g_cidx[b * LM + j];
            #pragma unroll
            for (int i = 0; i < 2; i++) {
                int xr = x0 + (ty << 1) + i;
                out[(b * LX + xr) * LM + m] = acc[i][jj];
            }
        }
    }
}

extern "C" void kernel_launch(void* const* d_in, const int* in_sizes, int n_in,
                              void* d_out, int out_size)
{
    const float* x      = (const float*)d_in[0];
    const float* memory = (const float*)d_in[1];
    const int*   mask   = (const int*)d_in[2];
    const float* W1     = (const float*)d_in[3];
    const float* b1     = (const float*)d_in[4];
    const float* W2     = (const float*)d_in[5];
    const float* Wt     = (const float*)d_in[6];
    float* out = (float*)d_out;

    fill_kernel<<<(BB * LX * LM / 4) / 256, 256>>>((float4*)out);
    compact_kernel<<<BB, 512>>>(mask);

    dim3 g1(32, D / 64, 2);
    gemm_qk<<<g1, 256>>>(x, W1, b1, memory, W2);

    // worst case: 8 column tiles per batch * 4 batches * 16 x-tiles = 512
    attn_kernel<<<512, 256>>>(Wt, out);
}

// round 12
// speedup vs baseline: 2.3562x; 1.3080x over previous
#include <cuda_runtime.h>
#include <cuda_fp16.h>

#define D   256
#define BB  4
#define LX  512
#define LM  512

// Scratch (allocation-free requirement -> device globals)
__device__ float g_Q[BB * LX * D];   // (b*LX + x, d)
__device__ float g_K[BB * LM * D];   // (b*LM + r, d), r = COMPACTED valid-m index
__device__ int   g_cidx[BB * LM];    // compacted -> original m index
__device__ __align__(16) int g_cnt[BB];  // valid count per batch

// ----------------------------------------------------------------------------
// Fill output with -10000 (masked default).
// ----------------------------------------------------------------------------
__global__ __launch_bounds__(256) void fill_kernel(float4* __restrict__ out) {
    int i = blockIdx.x * 256 + threadIdx.x;
    out[i] = make_float4(-10000.0f, -10000.0f, -10000.0f, -10000.0f);
}

// ----------------------------------------------------------------------------
// Compact mask: per batch, ballot-scan 512 entries -> cidx list + count.
// ----------------------------------------------------------------------------
__global__ __launch_bounds__(512) void compact_kernel(const int* __restrict__ mask) {
    int b = blockIdx.x;
    int t = threadIdx.x;
    int lane = t & 31, wid = t >> 5;

    int valid = (mask[b * LM + t] != 0);
    unsigned bal = __ballot_sync(0xffffffffu, valid);

    __shared__ int wcnt[16];
    __shared__ int woff[16];
    __shared__ int s_cnt;
    if (lane == 0) wcnt[wid] = __popc(bal);
    __syncthreads();
    if (t == 0) {
        int s = 0;
        #pragma unroll
        for (int i = 0; i < 16; i++) { woff[i] = s; s += wcnt[i]; }
        s_cnt = s;
        g_cnt[b] = s;
    }
    __syncthreads();
    int pos = woff[wid] + __popc(bal & ((1u << lane) - 1u));
    if (valid) g_cidx[b * LM + pos] = t;
    int cnt = s_cnt;
    int cpad = (cnt + 63) & ~63;
    if (t >= cnt && t < cpad) g_cidx[b * LM + t] = 0;
}

// ----------------------------------------------------------------------------
// Kernel A: projections. z==0: g_Q = x @ W1^T + b1 (all rows).
//           z==1: g_K[compacted] = memory[cidx] @ W2^T (valid rows only).
// Tile 64x64, BK=16, 4x4 per thread. (unchanged from passing round 9)
// ----------------------------------------------------------------------------
__global__ __launch_bounds__(256) void gemm_qk(
    const float* __restrict__ x,   const float* __restrict__ W1,
    const float* __restrict__ b1,  const float* __restrict__ mem,
    const float* __restrict__ W2)
{
    __shared__ float As[16][64];
    __shared__ float Bs[16][64];

    int tid = threadIdx.x;
    int n0 = blockIdx.y * 64;
    int tx = tid & 15;
    int ty = tid >> 4;
    int lr = tid >> 2;
    int lc = (tid & 3) << 2;

    const float* W; const float* bias; float* C;
    const float* Ap;
    int crow;

    if (blockIdx.z == 0) {
        int m0 = blockIdx.x * 64;
        W = W1; bias = b1; C = g_Q;
        Ap = x + (m0 + lr) * D + lc;
        crow = m0;
    } else {
        int b  = blockIdx.x >> 3;
        int rt = blockIdx.x & 7;
        if (rt * 64 >= g_cnt[b]) return;
        W = W2; bias = nullptr; C = g_K;
        int orig = g_cidx[b * LM + rt * 64 + lr];
        Ap = mem + (b * LM + orig) * D + lc;
        crow = b * LM + rt * 64;
    }

    float acc[4][4] = {};
    const float* Wp = W + (n0 + lr) * D + lc;

    for (int k0 = 0; k0 < D; k0 += 16) {
        float4 av = *(const float4*)(Ap + k0);
        float4 wv = *(const float4*)(Wp + k0);
        As[lc + 0][lr] = av.x; As[lc + 1][lr] = av.y;
        As[lc + 2][lr] = av.z; As[lc + 3][lr] = av.w;
        Bs[lc + 0][lr] = wv.x; Bs[lc + 1][lr] = wv.y;
        Bs[lc + 2][lr] = wv.z; Bs[lc + 3][lr] = wv.w;
        __syncthreads();
        #pragma unroll
        for (int k = 0; k < 16; k++) {
            float4 a4 = *(const float4*)&As[k][ty << 2];
            float4 b4 = *(const float4*)&Bs[k][tx << 2];
            float av4[4] = {a4.x, a4.y, a4.z, a4.w};
            float bv4[4] = {b4.x, b4.y, b4.z, b4.w};
            #pragma unroll
            for (int i = 0; i < 4; i++)
                #pragma unroll
                for (int j = 0; j < 4; j++)
                    acc[i][j] = fmaf(av4[i], bv4[j], acc[i][j]);
        }
        __syncthreads();
    }

    int n = n0 + (tx << 2);
    float bx = 0.f, by = 0.f, bz = 0.f, bw = 0.f;
    if (bias) { bx = bias[n]; by = bias[n + 1]; bz = bias[n + 2]; bw = bias[n + 3]; }
    #pragma unroll
    for (int i = 0; i < 4; i++) {
        int r = crow + (ty << 2) + i;
        float4 o;
        o.x = acc[i][0] + bx; o.y = acc[i][1] + by;
        o.z = acc[i][2] + bz; o.w = acc[i][3] + bw;
        *(float4*)&C[r * D + n] = o;
    }
}

// ----------------------------------------------------------------------------
// Kernel B: front-packed 1-D grid of 64x64 items, 512 threads, 2x4 micro-tile.
// fp32 smem + FADD; pack 2 row-sums -> tanh.approx.f16x2 -> HFMA2 accumulate.
// MUFU instruction count halved vs fp32 tanh.
// ----------------------------------------------------------------------------
__global__ __launch_bounds__(512) void attn_kernel(
    const float* __restrict__ Wt, float* __restrict__ out)
{
    int4 cv = *(const int4*)g_cnt;
    int n0t = (cv.x + 63) >> 6;
    int n1t = (cv.y + 63) >> 6;
    int n2t = (cv.z + 63) >> 6;
    int n3t = (cv.w + 63) >> 6;
    int total_tiles = n0t + n1t + n2t + n3t;

    int work = blockIdx.x;
    if (work >= (total_tiles << 3)) return;      // 8 x-tiles (64 rows) per col tile

    int tile = work >> 3;
    int xt   = work & 7;

    int b, mt, cnt;
    if (tile < n0t)                   { b = 0; mt = tile;                   cnt = cv.x; }
    else if (tile < n0t + n1t)        { b = 1; mt = tile - n0t;             cnt = cv.y; }
    else if (tile < n0t + n1t + n2t)  { b = 2; mt = tile - n0t - n1t;       cnt = cv.z; }
    else                              { b = 3; mt = tile - n0t - n1t - n2t; cnt = cv.w; }

    int m0 = mt << 6;      // compacted column base (64 wide)
    int x0 = xt << 6;      // x-row base (64 tall)

    __shared__ float   Qs[32][64];   // [k][x-row]
    __shared__ float   Ks[32][64];   // [k][m-col]
    __shared__ __half2 wts2[32];

    int tid = threadIdx.x;
    int tx = tid & 15;     // 16 groups * 4 cols
    int ty = tid >> 4;     // 32 groups * 2 rows

    const float* Qbase = g_Q + (b * LX + x0) * D;
    const float* Kbase = g_K + (b * LM + m0) * D;

    __half2 acc[4];
    acc[0] = __float2half2_rn(0.f); acc[1] = __float2half2_rn(0.f);
    acc[2] = __float2half2_rn(0.f); acc[3] = __float2half2_rn(0.f);

    int lr = tid >> 3;           // 0..63 load row
    int lc = (tid & 7) << 2;     // 0..28 k-offset

    for (int k0 = 0; k0 < D; k0 += 32) {
        if (tid < 32) wts2[tid] = __float2half2_rn(Wt[k0 + tid]);
        float4 qv = *(const float4*)(Qbase + lr * D + k0 + lc);
        Qs[lc + 0][lr] = qv.x; Qs[lc + 1][lr] = qv.y;
        Qs[lc + 2][lr] = qv.z; Qs[lc + 3][lr] = qv.w;
        float4 kv = *(const float4*)(Kbase + lr * D + k0 + lc);
        Ks[lc + 0][lr] = kv.x; Ks[lc + 1][lr] = kv.y;
        Ks[lc + 2][lr] = kv.z; Ks[lc + 3][lr] = kv.w;
        __syncthreads();
        #pragma unroll
        for (int k = 0; k < 32; k++) {
            float2 q2 = *(const float2*)&Qs[k][ty << 1];   // 2 rows
            float4 kb = *(const float4*)&Ks[k][tx << 2];   // 4 cols
            __half2 w2 = wts2[k];
            float kf[4] = {kb.x, kb.y, kb.z, kb.w};
            #pragma unroll
            for (int j = 0; j < 4; j++) {
                unsigned p;
                // pack: low half = row0 sum, high half = row1 sum
                asm("cvt.rn.f16x2.f32 %0, %1, %2;"
                    : "=r"(p) : "f"(q2.y + kf[j]), "f"(q2.x + kf[j]));
                asm("tanh.approx.f16x2 %0, %0;" : "+r"(p));
                acc[j] = __hfma2(w2, *reinterpret_cast<__half2*>(&p), acc[j]);
            }
        }
        __syncthreads();
    }

    // Scatter epilogue: compacted col j -> original column cidx[b][j]
    int xr = x0 + (ty << 1);
    #pragma unroll
    for (int j = 0; j < 4; j++) {
        int jc = m0 + (tx << 2) + j;
        if (jc < cnt) {
            int m = g_cidx[b * LM + jc];
            float2 f = __half22float2(acc[j]);   // x = low = row0, y = high = row1
            out[(b * LX + xr)     * LM + m] = f.x;
            out[(b * LX + xr + 1) * LM + m] = f.y;
        }
    }
}

extern "C" void kernel_launch(void* const* d_in, const int* in_sizes, int n_in,
                              void* d_out, int out_size)
{
    const float* x      = (const float*)d_in[0];
    const float* memory = (const float*)d_in[1];
    const int*   mask   = (const int*)d_in[2];
    const float* W1     = (const float*)d_in[3];
    const float* b1     = (const float*)d_in[4];
    const float* W2     = (const float*)d_in[5];
    const float* Wt     = (const float*)d_in[6];
    float* out = (float*)d_out;

    fill_kernel<<<(BB * LX * LM / 4) / 256, 256>>>((float4*)out);
    compact_kernel<<<BB, 512>>>(mask);

    dim3 g1(32, D / 64, 2);
    gemm_qk<<<g1, 256>>>(x, W1, b1, memory, W2);

    // worst case: 8 column tiles per batch * 4 batches * 8 x-tiles = 256
    attn_kernel<<<256, 512>>>(Wt, out);
}